// round 2
// baseline (speedup 1.0000x reference)
#include <cuda_runtime.h>

// Problem constants (fixed by the reference)
#define B_   1024
#define S_   336
#define C_   64
#define O_   168
#define T_   96
#define BT   64      // batch tile per block
#define XP   172     // row pitch (floats): 16B-aligned, conflict-free for LDS.128
#define XPV  43      // pitch in float4 units

#define SMEM_FLOATS (BT * XP + T_ * XP)
#define SMEM_BYTES  (SMEM_FLOATS * 4)

// Per block: one channel c, one 64-batch tile.
//   Y[b, t, c] = sum_o x[b, S-O+o, c] * W[c, o, t] + bias[c, t]
// 256 threads, 4(b) x 6(t) register tile, interleaved:
//   b = b0 + tb + i*16   (tb = tid % 16, i < 4)
//   t = tt + j*16        (tt = tid / 16, j < 6)
// k-loop unrolled by 4 with float4 LDS and 1-chunk A prefetch.
__global__ __launch_bounds__(256, 2)
void tcilr_kernel(const float* __restrict__ x,
                  const float* __restrict__ W,
                  const float* __restrict__ bias,
                  float* __restrict__ out)
{
    extern __shared__ float smem[];
    float* Xs = smem;              // [BT][XP], Xs[bb][o]
    float* Wt = smem + BT * XP;    // [T_][XP], Wt[t][o]  (W transposed)

    const int c   = blockIdx.x;
    const int b0  = blockIdx.y * BT;
    const int tid = threadIdx.x;

    // ---- load W[c] (coalesced read) and transpose into Wt[t][o] ----
    const float* Wc = W + (size_t)c * (O_ * T_);
    #pragma unroll 4
    for (int i = tid; i < O_ * T_; i += 256) {
        int o = i / T_;
        int t = i - o * T_;
        Wt[t * XP + o] = Wc[i];
    }

    // ---- load X tail: Xs[bb][o] = x[(b0+bb)*S*C + (S-O+o)*C + c] ----
    const float* xc = x + (size_t)(S_ - O_) * C_ + c;
    #pragma unroll 2
    for (int i = tid; i < BT * O_; i += 256) {
        int bb = i / O_;
        int o  = i - bb * O_;
        Xs[bb * XP + o] =
            xc[(size_t)(b0 + bb) * (S_ * C_) + (size_t)o * C_];
    }
    __syncthreads();

    const int tb = tid & 15;
    const int tt = tid >> 4;

    const float4* XsV = reinterpret_cast<const float4*>(Xs);
    const float4* WtV = reinterpret_cast<const float4*>(Wt);

    float acc[4][6];
    #pragma unroll
    for (int i = 0; i < 4; i++)
        #pragma unroll
        for (int j = 0; j < 6; j++)
            acc[i][j] = 0.0f;

    // ---- main loop over 42 chunks of 4 k's ----
    float4 a[4];
    #pragma unroll
    for (int i = 0; i < 4; i++)
        a[i] = XsV[(tb + i * 16) * XPV + 0];

    #pragma unroll 2
    for (int ch = 0; ch < (O_ / 4) - 1; ch++) {
        float4 w[6];
        #pragma unroll
        for (int j = 0; j < 6; j++)
            w[j] = WtV[(tt + j * 16) * XPV + ch];

        float4 na[4];
        #pragma unroll
        for (int i = 0; i < 4; i++)
            na[i] = XsV[(tb + i * 16) * XPV + ch + 1];

        #pragma unroll
        for (int i = 0; i < 4; i++)
            #pragma unroll
            for (int j = 0; j < 6; j++) {
                acc[i][j] = fmaf(a[i].x, w[j].x, acc[i][j]);
                acc[i][j] = fmaf(a[i].y, w[j].y, acc[i][j]);
                acc[i][j] = fmaf(a[i].z, w[j].z, acc[i][j]);
                acc[i][j] = fmaf(a[i].w, w[j].w, acc[i][j]);
            }

        #pragma unroll
        for (int i = 0; i < 4; i++)
            a[i] = na[i];
    }

    // last chunk (ch = 41)
    {
        const int ch = (O_ / 4) - 1;
        float4 w[6];
        #pragma unroll
        for (int j = 0; j < 6; j++)
            w[j] = WtV[(tt + j * 16) * XPV + ch];
        #pragma unroll
        for (int i = 0; i < 4; i++)
            #pragma unroll
            for (int j = 0; j < 6; j++) {
                acc[i][j] = fmaf(a[i].x, w[j].x, acc[i][j]);
                acc[i][j] = fmaf(a[i].y, w[j].y, acc[i][j]);
                acc[i][j] = fmaf(a[i].z, w[j].z, acc[i][j]);
                acc[i][j] = fmaf(a[i].w, w[j].w, acc[i][j]);
            }
    }

    // ---- epilogue: add bias, store out[b, t, c] ----
    #pragma unroll
    for (int j = 0; j < 6; j++) {
        const int t  = tt + j * 16;
        const float bv = bias[c * T_ + t];
        #pragma unroll
        for (int i = 0; i < 4; i++) {
            const int b = b0 + tb + i * 16;
            out[((size_t)b * T_ + t) * C_ + c] = acc[i][j] + bv;
        }
    }
}

extern "C" void kernel_launch(void* const* d_in, const int* in_sizes, int n_in,
                              void* d_out, int out_size)
{
    const float* x    = (const float*)d_in[0];  // [B, S, C] fp32
    const float* W    = (const float*)d_in[1];  // [C, O, T] fp32
    const float* bias = (const float*)d_in[2];  // [C, T]    fp32
    float* out = (float*)d_out;                 // [B, T, C] fp32

    cudaFuncSetAttribute(tcilr_kernel,
                         cudaFuncAttributeMaxDynamicSharedMemorySize,
                         SMEM_BYTES);

    dim3 grid(C_, B_ / BT);   // channel-fastest for L2 sector dedup on x
    tcilr_kernel<<<grid, 256, SMEM_BYTES>>>(x, W, bias, out);
}

// round 4
// speedup vs baseline: 1.8820x; 1.8820x over previous
#include <cuda_runtime.h>
#include <cuda_bf16.h>
#include <cstdint>

// ---------------- problem constants ----------------
#define B_   1024
#define S_   336
#define C_   64
#define O_   168
#define T_   96
#define KP   176            // K padded to 11 * 16
#define MT   128            // batches per GEMM CTA
#define PIT  200            // smem row pitch in bf16 (400 B): 100 fl ≡ 4 mod 32 banks

// ---------------- scratch (device globals; no allocs) ----------------
__device__ __nv_bfloat16 g_xhi[(size_t)C_ * B_ * O_];   // [c][b][o]
__device__ __nv_bfloat16 g_xlo[(size_t)C_ * B_ * O_];   // [c][b][o]
__device__ float         g_yT [(size_t)C_ * B_ * T_];   // [c][b][t]

// ================= T1: x[B,S,C] -> xT hi/lo [C,B,O] bf16 split =================
__global__ __launch_bounds__(256)
void t1_kernel(const float* __restrict__ x)
{
    __shared__ float smt[C_ * 169];               // [c][o], pitch 169 (9c+o banks)
    const int b = blockIdx.x;
    const float* xb = x + (size_t)b * (S_ * C_) + (size_t)(S_ - O_) * C_;

    #pragma unroll 4
    for (int i = threadIdx.x; i < O_ * C_; i += 256) {
        int o = i >> 6, c = i & 63;
        smt[c * 169 + o] = xb[i];                 // coalesced read, cf write
    }
    __syncthreads();

    // 1344 items: (c, 8-o chunk); writes 16B hi + 16B lo, 336B contiguous runs per (c,b)
    for (int idx = threadIdx.x; idx < C_ * 21; idx += 256) {
        int c  = idx / 21;
        int ch = idx - c * 21;
        const float* src = &smt[c * 169 + ch * 8];
        __nv_bfloat16 h8[8], l8[8];
        #pragma unroll
        for (int j = 0; j < 8; j++) {
            float f = src[j];
            __nv_bfloat16 h = __float2bfloat16(f);
            h8[j] = h;
            l8[j] = __float2bfloat16(f - __bfloat162float(h));
        }
        size_t base = ((size_t)c * B_ + b) * O_ + ch * 8;
        *(uint4*)(g_xhi + base) = *(const uint4*)h8;
        *(uint4*)(g_xlo + base) = *(const uint4*)l8;
    }
}

// ================= GEMM: (c, 128-batch) CTA, mma.sync bf16 split =================
// smem byte offsets
#define A_HI_OFF   0
#define A_LO_OFF   (MT * PIT * 2)                 // 51200
#define B_HI_OFF   (A_LO_OFF + MT * PIT * 2)      // 102400
#define B_LO_OFF   (B_HI_OFF + T_ * PIT * 2)      // 140800
#define BIAS_OFF   (B_LO_OFF + T_ * PIT * 2)      // 179200
#define SMEM_TOT   (BIAS_OFF + T_ * 4)            // 179584

__device__ __forceinline__ void mma16816(float* d, const uint32_t* a, const uint32_t* b)
{
    asm volatile(
        "mma.sync.aligned.m16n8k16.row.col.f32.bf16.bf16.f32 "
        "{%0,%1,%2,%3}, {%4,%5,%6,%7}, {%8,%9}, {%0,%1,%2,%3};"
        : "+f"(d[0]), "+f"(d[1]), "+f"(d[2]), "+f"(d[3])
        : "r"(a[0]), "r"(a[1]), "r"(a[2]), "r"(a[3]), "r"(b[0]), "r"(b[1]));
}

__global__ __launch_bounds__(256, 1)
void gemm_kernel(const float* __restrict__ W, const float* __restrict__ bias)
{
    extern __shared__ char smem[];
    const int c   = blockIdx.x;
    const int b0  = blockIdx.y * MT;
    const int tid = threadIdx.x;

    // ---- A fill: 128 rows x 21 uint4 (hi & lo), coalesced 16B ----
    {
        const uint4* ahi = (const uint4*)(g_xhi + ((size_t)c * B_ + b0) * O_);
        const uint4* alo = (const uint4*)(g_xlo + ((size_t)c * B_ + b0) * O_);
        for (int idx = tid; idx < MT * 21; idx += 256) {
            int r  = idx / 21;
            int ch = idx - r * 21;
            uint32_t d = r * (PIT * 2) + ch * 16;
            *(uint4*)(smem + A_HI_OFF + d) = ahi[idx];
            *(uint4*)(smem + A_LO_OFF + d) = alo[idx];
        }
        const uint4 z = make_uint4(0, 0, 0, 0);
        for (int idx = tid; idx < MT; idx += 256) {       // pad k 168..175
            uint32_t d = idx * (PIT * 2) + 21 * 16;
            *(uint4*)(smem + A_HI_OFF + d) = z;
            *(uint4*)(smem + A_LO_OFF + d) = z;
        }
    }
    // ---- B fill: W[c][o][t] -> Bs[t][o] transposed + split ----
    {
        const float* Wc = W + (size_t)c * (O_ * T_);
        for (int idx = tid; idx < O_ * T_; idx += 256) {
            int o = idx / T_, t = idx - o * T_;
            float f = Wc[idx];                             // coalesced read
            __nv_bfloat16 h = __float2bfloat16(f);
            uint32_t d = t * (PIT * 2) + o * 2;
            *(__nv_bfloat16*)(smem + B_HI_OFF + d) = h;
            *(__nv_bfloat16*)(smem + B_LO_OFF + d) = __float2bfloat16(f - __bfloat162float(h));
        }
        for (int idx = tid; idx < T_ * 8; idx += 256) {    // pad k 168..175
            int t = idx >> 3, o = O_ + (idx & 7);
            uint32_t d = t * (PIT * 2) + o * 2;
            *(__nv_bfloat16*)(smem + B_HI_OFF + d) = __float2bfloat16(0.f);
            *(__nv_bfloat16*)(smem + B_LO_OFF + d) = __float2bfloat16(0.f);
        }
        if (tid < T_)
            *(float*)(smem + BIAS_OFF + tid * 4) = bias[c * T_ + tid];
    }
    __syncthreads();

    // ---- warp tiling: 4(m) x 2(n) warps; warp = 32 rows x 48 cols ----
    const int lane = tid & 31;
    const int wid  = tid >> 5;
    const int wm   = wid & 3;          // m block (32 rows)
    const int wn   = wid >> 2;         // n block (48 cols)
    const int grp  = lane >> 2;        // 0..7
    const int qid  = lane & 3;         // 0..3

    float acc[2][6][4];
    #pragma unroll
    for (int mi = 0; mi < 2; mi++)
        #pragma unroll
        for (int ni = 0; ni < 6; ni++)
            #pragma unroll
            for (int r = 0; r < 4; r++)
                acc[mi][ni][r] = 0.f;

    const char* pA[3] = { smem + A_HI_OFF, smem + A_HI_OFF, smem + A_LO_OFF };
    const char* pB[3] = { smem + B_HI_OFF, smem + B_LO_OFF, smem + B_HI_OFF };

    #pragma unroll
    for (int p = 0; p < 3; p++) {
        const char* Ab = pA[p] + (wm * 32 + grp) * (PIT * 2) + qid * 4;
        const char* Bb = pB[p] + (wn * 48 + grp) * (PIT * 2) + qid * 4;
        for (int ks = 0; ks < KP / 16; ks++) {
            const int k2 = ks * 32;    // k0 * 2 bytes
            uint32_t afr[2][4];
            #pragma unroll
            for (int mi = 0; mi < 2; mi++) {
                const char* a = Ab + mi * 16 * (PIT * 2) + k2;
                afr[mi][0] = *(const uint32_t*)(a);
                afr[mi][1] = *(const uint32_t*)(a + 8 * (PIT * 2));
                afr[mi][2] = *(const uint32_t*)(a + 16);
                afr[mi][3] = *(const uint32_t*)(a + 8 * (PIT * 2) + 16);
            }
            #pragma unroll
            for (int ni = 0; ni < 6; ni++) {
                const char* b = Bb + ni * 8 * (PIT * 2) + k2;
                uint32_t bfr[2];
                bfr[0] = *(const uint32_t*)(b);
                bfr[1] = *(const uint32_t*)(b + 16);
                mma16816(acc[0][ni], afr[0], bfr);
                mma16816(acc[1][ni], afr[1], bfr);
            }
        }
    }

    // ---- epilogue: bias + store yT[c][b][t] ----
    const float* bs = (const float*)(smem + BIAS_OFF);
    #pragma unroll
    for (int mi = 0; mi < 2; mi++) {
        const int b = b0 + wm * 32 + mi * 16 + grp;
        float* y0 = g_yT + ((size_t)c * B_ + b) * T_;
        float* y1 = y0 + 8 * T_;
        #pragma unroll
        for (int ni = 0; ni < 6; ni++) {
            const int t = wn * 48 + ni * 8 + qid * 2;
            float2 v0 = { acc[mi][ni][0] + bs[t], acc[mi][ni][1] + bs[t + 1] };
            float2 v1 = { acc[mi][ni][2] + bs[t], acc[mi][ni][3] + bs[t + 1] };
            *(float2*)(y0 + t) = v0;
            *(float2*)(y1 + t) = v1;
        }
    }
}

// ================= T2: yT[C, B*T] -> out[B*T, C] =================
__global__ __launch_bounds__(256)
void t2_kernel(float* __restrict__ out)
{
    __shared__ float tile[64][65];
    const int bt0 = blockIdx.x * 64;
    const int col = threadIdx.x & 63;
    const int r0  = threadIdx.x >> 6;
    #pragma unroll
    for (int i = 0; i < 16; i++) {
        int cc = r0 + i * 4;
        tile[cc][col] = g_yT[(size_t)cc * (B_ * T_) + bt0 + col];   // coalesced
    }
    __syncthreads();
    #pragma unroll
    for (int i = 0; i < 16; i++) {
        int row = r0 + i * 4;
        out[(size_t)(bt0 + row) * C_ + col] = tile[col][row];       // coalesced
    }
}

// ================= launch =================
extern "C" void kernel_launch(void* const* d_in, const int* in_sizes, int n_in,
                              void* d_out, int out_size)
{
    const float* x    = (const float*)d_in[0];  // [B, S, C]
    const float* W    = (const float*)d_in[1];  // [C, O, T]
    const float* bias = (const float*)d_in[2];  // [C, T]
    float* out = (float*)d_out;                 // [B, T, C]

    cudaFuncSetAttribute(gemm_kernel,
                         cudaFuncAttributeMaxDynamicSharedMemorySize, SMEM_TOT);

    t1_kernel<<<B_, 256>>>(x);
    gemm_kernel<<<dim3(C_, B_ / MT), 256, SMEM_TOT>>>(W, bias);
    t2_kernel<<<(B_ * T_) / 64, 256>>>(out);
}

// round 5
// speedup vs baseline: 2.1152x; 1.1239x over previous
#include <cuda_runtime.h>
#include <cuda_bf16.h>
#include <cstdint>

// ---------------- problem constants ----------------
#define B_   1024
#define S_   336
#define C_   64
#define O_   168
#define T_   96
#define KP   176            // K padded to 11 * 16
#define MT   128            // batches per GEMM CTA

// ---------------- scratch (device globals; no allocs) ----------------
__device__ __nv_bfloat16 g_xhi[(size_t)C_ * B_ * O_];   // [c][b][o]
__device__ __nv_bfloat16 g_xlo[(size_t)C_ * B_ * O_];   // [c][b][o]
__device__ float         g_yT [(size_t)C_ * B_ * T_];   // [c][b][t]

// split f into bf16 hi + bf16 lo (pairwise, packed)
__device__ __forceinline__ void split2(float f0, float f1, uint32_t& h, uint32_t& l)
{
    __nv_bfloat162 hb = __floats2bfloat162_rn(f0, f1);   // .x = f0 (low half)
    float r0 = f0 - __bfloat162float(hb.x);
    float r1 = f1 - __bfloat162float(hb.y);
    __nv_bfloat162 lb = __floats2bfloat162_rn(r0, r1);
    h = *reinterpret_cast<uint32_t*>(&hb);
    l = *reinterpret_cast<uint32_t*>(&lb);
}

// ================= T1: x[B,S,C] -> xT hi/lo [C,B,O], split by 32-channel half =================
__global__ __launch_bounds__(256)
void t1_kernel(const float* __restrict__ x)
{
    __shared__ float smt[32 * 172];               // [c_local][o], pitch 172
    const int b    = blockIdx.x;
    const int half = blockIdx.y;                  // channels half*32 .. +31
    const uint4* xb = reinterpret_cast<const uint4*>(
        x + (size_t)b * (S_ * C_) + (size_t)(S_ - O_) * C_);

    // load: 168 rows x 8 uint4 (this half's 32 channels), coalesced
    for (int i = threadIdx.x; i < O_ * 8; i += 256) {
        int o = i >> 3, q = i & 7;
        uint4 v = xb[o * 16 + half * 8 + q];
        float* d = &smt[(q * 4) * 172 + o];
        d[0 * 172] = __uint_as_float(v.x);
        d[1 * 172] = __uint_as_float(v.y);
        d[2 * 172] = __uint_as_float(v.z);
        d[3 * 172] = __uint_as_float(v.w);
    }
    __syncthreads();

    // convert: 32 c x 21 chunks of 8 o
    for (int idx = threadIdx.x; idx < 32 * 21; idx += 256) {
        int cl = idx / 21, ch = idx - cl * 21;
        const float* src = &smt[cl * 172 + ch * 8];
        float4 f0 = *(const float4*)(src);
        float4 f1 = *(const float4*)(src + 4);
        uint4 hw, lw;
        split2(f0.x, f0.y, hw.x, lw.x);
        split2(f0.z, f0.w, hw.y, lw.y);
        split2(f1.x, f1.y, hw.z, lw.z);
        split2(f1.z, f1.w, hw.w, lw.w);
        size_t base = ((size_t)(half * 32 + cl) * B_ + b) * O_ + ch * 8;
        *(uint4*)(g_xhi + base) = hw;
        *(uint4*)(g_xlo + base) = lw;
    }
}

// ================= GEMM: (c, 128-batch) CTA, fused 3-pass bf16-split, ldmatrix =================
// smem byte offsets:  A pitch 400 B (conflict-free granules), B pitch 512 B + chunk-XOR swizzle
#define APIT   400
#define BPIT   512
#define A_HI   0
#define A_LO   (MT * APIT)                        // 51200
#define B_HI   (A_LO + MT * APIT)                 // 102400
#define B_LO   (B_HI + T_ * BPIT)                 // 151552
#define SMEM_TOT (B_LO + T_ * BPIT)               // 200704

__device__ __forceinline__ void mma16816(float* d, const uint32_t* a, const uint32_t* b)
{
    asm volatile(
        "mma.sync.aligned.m16n8k16.row.col.f32.bf16.bf16.f32 "
        "{%0,%1,%2,%3}, {%4,%5,%6,%7}, {%8,%9}, {%0,%1,%2,%3};"
        : "+f"(d[0]), "+f"(d[1]), "+f"(d[2]), "+f"(d[3])
        : "r"(a[0]), "r"(a[1]), "r"(a[2]), "r"(a[3]), "r"(b[0]), "r"(b[1]));
}
__device__ __forceinline__ void ldsm4(uint32_t* r, uint32_t addr)
{
    asm volatile("ldmatrix.sync.aligned.m8n8.x4.shared.b16 {%0,%1,%2,%3}, [%4];"
                 : "=r"(r[0]), "=r"(r[1]), "=r"(r[2]), "=r"(r[3]) : "r"(addr));
}
__device__ __forceinline__ uint32_t smem_u32(const void* p) {
    uint32_t a;
    asm("{ .reg .u64 t; cvta.to.shared.u64 t, %1; cvt.u32.u64 %0, t; }" : "=r"(a) : "l"(p));
    return a;
}

__global__ __launch_bounds__(256, 1)
void gemm_kernel(const float* __restrict__ W, const float* __restrict__ bias)
{
    extern __shared__ char smem[];
    const uint32_t sb = smem_u32(smem);
    const int c   = blockIdx.x;
    const int b0  = blockIdx.y * MT;
    const int tid = threadIdx.x;

    // ---- A fill: 128 rows x 22 chunks of 16B (hi & lo), row 21 = zero pad ----
    {
        const uint4* ahi = (const uint4*)(g_xhi + ((size_t)c * B_ + b0) * O_);
        const uint4* alo = (const uint4*)(g_xlo + ((size_t)c * B_ + b0) * O_);
        const uint4 z = make_uint4(0, 0, 0, 0);
        for (int idx = tid; idx < MT * 22; idx += 256) {
            int r  = idx / 22;
            int ch = idx - r * 22;
            uint32_t d = r * APIT + ch * 16;
            uint4 vh = (ch < 21) ? ahi[r * 21 + ch] : z;
            uint4 vl = (ch < 21) ? alo[r * 21 + ch] : z;
            *(uint4*)(smem + A_HI + d) = vh;
            *(uint4*)(smem + A_LO + d) = vl;
        }
    }
    // ---- B fill: W[c][o][t] -> Bs[t][o] (swizzled 512B rows), 4-o granules ----
    {
        const float* Wc = W + (size_t)c * (O_ * T_);
        for (int idx = tid; idx < 44 * T_; idx += 256) {
            int oq = idx / T_;                     // group of 4 o's
            int t  = idx - oq * T_;
            int o  = oq * 4;
            float f0 = (o + 0 < O_) ? Wc[(o + 0) * T_ + t] : 0.f;
            float f1 = (o + 1 < O_) ? Wc[(o + 1) * T_ + t] : 0.f;
            float f2 = (o + 2 < O_) ? Wc[(o + 2) * T_ + t] : 0.f;
            float f3 = (o + 3 < O_) ? Wc[(o + 3) * T_ + t] : 0.f;
            uint2 hv, lv;
            split2(f0, f1, hv.x, lv.x);
            split2(f2, f3, hv.y, lv.y);
            int chunk = oq >> 1;
            uint32_t d = t * BPIT + ((chunk ^ (t & 7)) << 4) + ((oq & 1) << 3);
            *(uint2*)(smem + B_HI + d) = hv;
            *(uint2*)(smem + B_LO + d) = lv;
        }
    }
    __syncthreads();

    // ---- warp tiling: 4(m) x 2(n); warp = 32 rows x 48 cols ----
    const int lane = tid & 31;
    const int wid  = tid >> 5;
    const int wm   = wid & 3;
    const int wn   = wid >> 2;
    const int grp  = lane >> 2;
    const int qid  = lane & 3;

    // per-lane ldmatrix addresses
    const uint32_t aRowH = sb + A_HI + (wm * 32 + (lane & 15)) * APIT + ((lane >> 4) << 4);
    const uint32_t aRowL = aRowH + (A_LO - A_HI);
    const int tl   = (lane & 7) + ((lane >> 4) << 3);  // row within n-pair
    const int cbit = (lane >> 3) & 1;                  // k-chunk select
    uint32_t bRow[3];
    int      bT7[3];
    #pragma unroll
    for (int j = 0; j < 3; j++) {
        int t = wn * 48 + j * 16 + tl;
        bRow[j] = sb + B_HI + t * BPIT;
        bT7[j]  = t & 7;
    }

    float acc[2][6][4];
    #pragma unroll
    for (int mi = 0; mi < 2; mi++)
        #pragma unroll
        for (int ni = 0; ni < 6; ni++)
            #pragma unroll
            for (int r = 0; r < 4; r++)
                acc[mi][ni][r] = 0.f;

    // ---- fused k loop: hi*hi + hi*lo + lo*hi per kstep ----
    #pragma unroll
    for (int ks = 0; ks < KP / 16; ks++) {
        uint32_t ah[2][4], al[2][4], bh[3][4], bl[3][4];
        const uint32_t ka = ks * 32;
        ldsm4(ah[0], aRowH + ka);
        ldsm4(ah[1], aRowH + 16 * APIT + ka);
        ldsm4(al[0], aRowL + ka);
        ldsm4(al[1], aRowL + 16 * APIT + ka);
        #pragma unroll
        for (int j = 0; j < 3; j++) {
            uint32_t sc = (uint32_t)(((2 * ks + cbit) ^ bT7[j]) << 4);
            ldsm4(bh[j], bRow[j] + sc);
            ldsm4(bl[j], bRow[j] + (B_LO - B_HI) + sc);
        }
        #pragma unroll
        for (int j = 0; j < 3; j++)
            #pragma unroll
            for (int h = 0; h < 2; h++) {
                const int ni = 2 * j + h;
                const uint32_t* bhf = &bh[j][2 * h];
                const uint32_t* blf = &bl[j][2 * h];
                #pragma unroll
                for (int mi = 0; mi < 2; mi++) {
                    mma16816(acc[mi][ni], ah[mi], bhf);   // hi*hi
                    mma16816(acc[mi][ni], ah[mi], blf);   // hi*lo
                    mma16816(acc[mi][ni], al[mi], bhf);   // lo*hi
                }
            }
    }

    // ---- epilogue: bias + store yT[c][b][t] ----
    const float* bc = bias + c * T_;
    #pragma unroll
    for (int mi = 0; mi < 2; mi++) {
        const int b = b0 + wm * 32 + mi * 16 + grp;
        float* y0 = g_yT + ((size_t)c * B_ + b) * T_;
        float* y1 = y0 + 8 * T_;
        #pragma unroll
        for (int ni = 0; ni < 6; ni++) {
            const int t = wn * 48 + ni * 8 + qid * 2;
            const float bv0 = __ldg(bc + t);
            const float bv1 = __ldg(bc + t + 1);
            float2 v0 = { acc[mi][ni][0] + bv0, acc[mi][ni][1] + bv1 };
            float2 v1 = { acc[mi][ni][2] + bv0, acc[mi][ni][3] + bv1 };
            *(float2*)(y0 + t) = v0;
            *(float2*)(y1 + t) = v1;
        }
    }
}

// ================= T2: yT[C, B*T] -> out[B*T, C], float4 both sides =================
__global__ __launch_bounds__(256)
void t2_kernel(float* __restrict__ out)
{
    __shared__ float tile[64 * 69];               // pitch 69
    const int bt0 = blockIdx.x * 64;

    #pragma unroll
    for (int i = threadIdx.x; i < 1024; i += 256) {
        int cc = i >> 4, q = i & 15;
        float4 v = *(const float4*)&g_yT[(size_t)cc * (B_ * T_) + bt0 + q * 4];
        float* d = &tile[cc * 69 + q * 4];
        d[0] = v.x; d[1] = v.y; d[2] = v.z; d[3] = v.w;
    }
    __syncthreads();
    #pragma unroll
    for (int i = threadIdx.x; i < 1024; i += 256) {
        int r = i >> 4, cq = i & 15;
        float4 v;
        v.x = tile[(cq * 4 + 0) * 69 + r];
        v.y = tile[(cq * 4 + 1) * 69 + r];
        v.z = tile[(cq * 4 + 2) * 69 + r];
        v.w = tile[(cq * 4 + 3) * 69 + r];
        *(float4*)&out[(size_t)(bt0 + r) * C_ + cq * 4] = v;
    }
}

// ================= launch =================
extern "C" void kernel_launch(void* const* d_in, const int* in_sizes, int n_in,
                              void* d_out, int out_size)
{
    const float* x    = (const float*)d_in[0];  // [B, S, C]
    const float* W    = (const float*)d_in[1];  // [C, O, T]
    const float* bias = (const float*)d_in[2];  // [C, T]
    float* out = (float*)d_out;                 // [B, T, C]

    cudaFuncSetAttribute(gemm_kernel,
                         cudaFuncAttributeMaxDynamicSharedMemorySize, SMEM_TOT);

    t1_kernel<<<dim3(B_, 2), 256>>>(x);
    gemm_kernel<<<dim3(C_, B_ / MT), 256, SMEM_TOT>>>(W, bias);
    t2_kernel<<<(B_ * T_) / 64, 256>>>(out);
}

// round 6
// speedup vs baseline: 2.7934x; 1.3207x over previous
#include <cuda_runtime.h>
#include <cuda_bf16.h>
#include <cstdint>

// ---------------- problem constants ----------------
#define B_   1024
#define S_   336
#define C_   64
#define O_   168
#define T_   96
#define O2   192            // K padded to 3 chunks of 64
#define CH   64             // k per chunk
#define NCH  3
#define MT   128            // batches per GEMM CTA

// ---------------- scratch (device globals; no allocs) ----------------
__device__ __nv_bfloat16 g_xhi[(size_t)C_ * B_ * O2];       // [c][b][o]  (o padded w/ zeros)
__device__ __nv_bfloat16 g_xlo[(size_t)C_ * B_ * O2];
__device__ unsigned char g_bhi[(size_t)C_ * NCH * T_ * 128];// pre-swizzled W hi image
__device__ unsigned char g_blo[(size_t)C_ * NCH * T_ * 128];
__device__ float         g_yT [(size_t)C_ * B_ * T_];       // [c][b][t]

// split f into bf16 hi + bf16 lo (pairwise, packed)
__device__ __forceinline__ void split2(float f0, float f1, uint32_t& h, uint32_t& l)
{
    __nv_bfloat162 hb = __floats2bfloat162_rn(f0, f1);
    float r0 = f0 - __bfloat162float(hb.x);
    float r1 = f1 - __bfloat162float(hb.y);
    __nv_bfloat162 lb = __floats2bfloat162_rn(r0, r1);
    h = *reinterpret_cast<uint32_t*>(&hb);
    l = *reinterpret_cast<uint32_t*>(&lb);
}
__device__ __forceinline__ uint32_t smem_u32(const void* p) {
    uint32_t a;
    asm("{ .reg .u64 t; cvta.to.shared.u64 t, %1; cvt.u32.u64 %0, t; }" : "=r"(a) : "l"(p));
    return a;
}
__device__ __forceinline__ void mma16816(float* d, const uint32_t* a, const uint32_t* b)
{
    asm volatile(
        "mma.sync.aligned.m16n8k16.row.col.f32.bf16.bf16.f32 "
        "{%0,%1,%2,%3}, {%4,%5,%6,%7}, {%8,%9}, {%0,%1,%2,%3};"
        : "+f"(d[0]), "+f"(d[1]), "+f"(d[2]), "+f"(d[3])
        : "r"(a[0]), "r"(a[1]), "r"(a[2]), "r"(a[3]), "r"(b[0]), "r"(b[1]));
}
__device__ __forceinline__ void ldsm4(uint32_t* r, uint32_t addr)
{
    asm volatile("ldmatrix.sync.aligned.m8n8.x4.shared.b16 {%0,%1,%2,%3}, [%4];"
                 : "=r"(r[0]), "=r"(r[1]), "=r"(r[2]), "=r"(r[3]) : "r"(addr));
}
#define CPA16(dst, src) \
    asm volatile("cp.async.cg.shared.global [%0], [%1], 16;" :: "r"(dst), "l"(src))
#define CPA_COMMIT() asm volatile("cp.async.commit_group;" ::: "memory")
#define CPA_WAIT(n)  asm volatile("cp.async.wait_group %0;" :: "n"(n) : "memory")

// ================= T0: W[c][o][t] -> pre-swizzled bf16 hi/lo images =================
__global__ __launch_bounds__(256)
void t0_kernel(const float* __restrict__ W)
{
    const int c = blockIdx.x;
    const float* Wc = W + (size_t)c * (O_ * T_);
    for (int idx = threadIdx.x; idx < 48 * T_; idx += 256) {
        int oq = idx / T_;                   // group of 4 o's, 0..47
        int t  = idx - oq * T_;
        int o  = oq * 4;
        float f0 = (o + 0 < O_) ? Wc[(o + 0) * T_ + t] : 0.f;
        float f1 = (o + 1 < O_) ? Wc[(o + 1) * T_ + t] : 0.f;
        float f2 = (o + 2 < O_) ? Wc[(o + 2) * T_ + t] : 0.f;
        float f3 = (o + 3 < O_) ? Wc[(o + 3) * T_ + t] : 0.f;
        uint2 hv, lv;
        split2(f0, f1, hv.x, lv.x);
        split2(f2, f3, hv.y, lv.y);
        int chunk = o >> 6;
        int kc    = o & 63;
        uint32_t off = (((uint32_t)(c * NCH + chunk) * T_ + t) << 7)
                     + (((uint32_t)(kc >> 3) ^ (t & 7)) << 4) + ((kc >> 2) & 1) * 8;
        *(uint2*)(g_bhi + off) = hv;
        *(uint2*)(g_blo + off) = lv;
    }
}

// ================= T1: x[B,S,C] -> xT hi/lo [C,B,O2] (zero-padded K) =================
__global__ __launch_bounds__(256)
void t1_kernel(const float* __restrict__ x)
{
    __shared__ float smt[32 * 172];
    const int b    = blockIdx.x;
    const int half = blockIdx.y;
    const uint4* xb = reinterpret_cast<const uint4*>(
        x + (size_t)b * (S_ * C_) + (size_t)(S_ - O_) * C_);

    for (int i = threadIdx.x; i < O_ * 8; i += 256) {
        int o = i >> 3, q = i & 7;
        uint4 v = xb[o * 16 + half * 8 + q];
        float* d = &smt[(q * 4) * 172 + o];
        d[0 * 172] = __uint_as_float(v.x);
        d[1 * 172] = __uint_as_float(v.y);
        d[2 * 172] = __uint_as_float(v.z);
        d[3 * 172] = __uint_as_float(v.w);
    }
    __syncthreads();

    // 32 c x 24 chunks of 8 o (chunks 21..23 are zero pad)
    for (int idx = threadIdx.x; idx < 32 * 24; idx += 256) {
        int cl = idx / 24, ch = idx - cl * 24;
        uint4 hw = make_uint4(0, 0, 0, 0), lw = make_uint4(0, 0, 0, 0);
        if (ch < 21) {
            const float* src = &smt[cl * 172 + ch * 8];
            float4 f0 = *(const float4*)(src);
            float4 f1 = *(const float4*)(src + 4);
            split2(f0.x, f0.y, hw.x, lw.x);
            split2(f0.z, f0.w, hw.y, lw.y);
            split2(f1.x, f1.y, hw.z, lw.z);
            split2(f1.z, f1.w, hw.w, lw.w);
        }
        size_t base = ((size_t)(half * 32 + cl) * B_ + b) * O2 + ch * 8;
        *(uint4*)(g_xhi + base) = hw;
        *(uint4*)(g_xlo + base) = lw;
    }
}

// ================= GEMM: cp.async double-buffered, 3 k-chunks, 2 CTAs/SM =================
// stage layout (bytes): A_hi 16K | A_lo 16K | B_hi 12K | B_lo 12K  = 56K; 2 stages = 112K
#define OFF_AHI  0
#define OFF_ALO  16384
#define OFF_BHI  32768
#define OFF_BLO  45056
#define STG      57344
#define SMEM_TOT (2 * STG)

__device__ __forceinline__ void fill_chunk(uint32_t sbase, int c, int b0, int chunk, int tid)
{
    const char* axh = (const char*)g_xhi
        + ((size_t)((c << 10) + b0) * O2 + (size_t)chunk * CH) * 2;
    const char* axl = (const char*)g_xlo
        + ((size_t)((c << 10) + b0) * O2 + (size_t)chunk * CH) * 2;
    #pragma unroll
    for (int it = 0; it < 4; it++) {
        int i = tid + it * 256;
        int r = i >> 3, cq = i & 7;
        uint32_t sw = (uint32_t)r * 128 + (((uint32_t)cq ^ (r & 7)) << 4);
        CPA16(sbase + OFF_AHI + sw, axh + (size_t)r * (O2 * 2) + cq * 16);
        CPA16(sbase + OFF_ALO + sw, axl + (size_t)r * (O2 * 2) + cq * 16);
    }
    const char* bh = (const char*)g_bhi + (size_t)(c * NCH + chunk) * (T_ * 128);
    const char* bl = (const char*)g_blo + (size_t)(c * NCH + chunk) * (T_ * 128);
    #pragma unroll
    for (int it = 0; it < 3; it++) {
        int i = tid + it * 256;
        CPA16(sbase + OFF_BHI + i * 16, bh + (size_t)i * 16);
        CPA16(sbase + OFF_BLO + i * 16, bl + (size_t)i * 16);
    }
}

__device__ __forceinline__ void mma_chunk(uint32_t base, int wm, int wn, int lane,
                                          float (*acc)[6][4])
{
    const int l7   = lane & 7;
    const int hi16 = lane >> 4;
    const int cbit = (lane >> 3) & 1;
    const int rA0  = wm * 32 + (lane & 15);
    const int tl   = l7 + (hi16 << 3);

    #pragma unroll
    for (int ks = 0; ks < 4; ks++) {
        uint32_t ah[2][4], al[2][4], bh[3][4], bl[3][4];
        const int kqa = ks * 2 + hi16;
        uint32_t sa = base + OFF_AHI + (uint32_t)rA0 * 128 + (((uint32_t)(kqa ^ l7)) << 4);
        ldsm4(ah[0], sa);
        ldsm4(ah[1], sa + 16 * 128);
        uint32_t sl = sa + (OFF_ALO - OFF_AHI);
        ldsm4(al[0], sl);
        ldsm4(al[1], sl + 16 * 128);
        const int kqb = ks * 2 + cbit;
        #pragma unroll
        for (int j = 0; j < 3; j++) {
            int t = wn * 48 + j * 16 + tl;
            uint32_t sbb = base + OFF_BHI + (uint32_t)t * 128 + (((uint32_t)(kqb ^ l7)) << 4);
            ldsm4(bh[j], sbb);
            ldsm4(bl[j], sbb + (OFF_BLO - OFF_BHI));
        }
        #pragma unroll
        for (int j = 0; j < 3; j++)
            #pragma unroll
            for (int h = 0; h < 2; h++) {
                const uint32_t* bhf = &bh[j][2 * h];
                const uint32_t* blf = &bl[j][2 * h];
                #pragma unroll
                for (int mi = 0; mi < 2; mi++) {
                    mma16816(acc[mi][2 * j + h], ah[mi], bhf);   // hi*hi
                    mma16816(acc[mi][2 * j + h], ah[mi], blf);   // hi*lo
                    mma16816(acc[mi][2 * j + h], al[mi], bhf);   // lo*hi
                }
            }
    }
}

__global__ __launch_bounds__(256, 2)
void gemm_kernel(const float* __restrict__ bias)
{
    extern __shared__ char smem[];
    const uint32_t sb = smem_u32(smem);
    const int c    = blockIdx.x;
    const int b0   = blockIdx.y * MT;
    const int tid  = threadIdx.x;
    const int lane = tid & 31;
    const int wid  = tid >> 5;
    const int wm   = wid & 3;
    const int wn   = wid >> 2;
    const int grp  = lane >> 2;
    const int qid  = lane & 3;

    float acc[2][6][4];
    #pragma unroll
    for (int mi = 0; mi < 2; mi++)
        #pragma unroll
        for (int ni = 0; ni < 6; ni++)
            #pragma unroll
            for (int r = 0; r < 4; r++)
                acc[mi][ni][r] = 0.f;

    // ---- software pipeline: 3 chunks, 2 stages ----
    fill_chunk(sb,        c, b0, 0, tid); CPA_COMMIT();
    fill_chunk(sb + STG,  c, b0, 1, tid); CPA_COMMIT();
    CPA_WAIT(1);
    __syncthreads();
    mma_chunk(sb, wm, wn, lane, acc);            // chunk 0
    __syncthreads();
    fill_chunk(sb,        c, b0, 2, tid); CPA_COMMIT();
    CPA_WAIT(1);
    __syncthreads();
    mma_chunk(sb + STG, wm, wn, lane, acc);      // chunk 1
    CPA_WAIT(0);
    __syncthreads();
    mma_chunk(sb, wm, wn, lane, acc);            // chunk 2

    // ---- epilogue: bias + store yT[c][b][t] ----
    const float* bc = bias + c * T_;
    #pragma unroll
    for (int mi = 0; mi < 2; mi++) {
        const int b = b0 + wm * 32 + mi * 16 + grp;
        float* y0 = g_yT + ((size_t)c * B_ + b) * T_;
        float* y1 = y0 + 8 * T_;
        #pragma unroll
        for (int ni = 0; ni < 6; ni++) {
            const int t = wn * 48 + ni * 8 + qid * 2;
            const float bv0 = __ldg(bc + t);
            const float bv1 = __ldg(bc + t + 1);
            float2 v0 = { acc[mi][ni][0] + bv0, acc[mi][ni][1] + bv1 };
            float2 v1 = { acc[mi][ni][2] + bv0, acc[mi][ni][3] + bv1 };
            *(float2*)(y0 + t) = v0;
            *(float2*)(y1 + t) = v1;
        }
    }
}

// ================= T2: yT[C, B*T] -> out[B*T, C], float4 both sides =================
__global__ __launch_bounds__(256)
void t2_kernel(float* __restrict__ out)
{
    __shared__ float tile[64 * 69];
    const int bt0 = blockIdx.x * 64;

    #pragma unroll
    for (int i = threadIdx.x; i < 1024; i += 256) {
        int cc = i >> 4, q = i & 15;
        float4 v = *(const float4*)&g_yT[(size_t)cc * (B_ * T_) + bt0 + q * 4];
        float* d = &tile[cc * 69 + q * 4];
        d[0] = v.x; d[1] = v.y; d[2] = v.z; d[3] = v.w;
    }
    __syncthreads();
    #pragma unroll
    for (int i = threadIdx.x; i < 1024; i += 256) {
        int r = i >> 4, cq = i & 15;
        float4 v;
        v.x = tile[(cq * 4 + 0) * 69 + r];
        v.y = tile[(cq * 4 + 1) * 69 + r];
        v.z = tile[(cq * 4 + 2) * 69 + r];
        v.w = tile[(cq * 4 + 3) * 69 + r];
        *(float4*)&out[(size_t)(bt0 + r) * C_ + cq * 4] = v;
    }
}

// ================= launch =================
extern "C" void kernel_launch(void* const* d_in, const int* in_sizes, int n_in,
                              void* d_out, int out_size)
{
    const float* x    = (const float*)d_in[0];  // [B, S, C]
    const float* W    = (const float*)d_in[1];  // [C, O, T]
    const float* bias = (const float*)d_in[2];  // [C, T]
    float* out = (float*)d_out;                 // [B, T, C]

    cudaFuncSetAttribute(gemm_kernel,
                         cudaFuncAttributeMaxDynamicSharedMemorySize, SMEM_TOT);

    t0_kernel<<<C_, 256>>>(W);
    t1_kernel<<<dim3(B_, 2), 256>>>(x);
    gemm_kernel<<<dim3(C_, B_ / MT), 256, SMEM_TOT>>>(bias);
    t2_kernel<<<(B_ * T_) / 64, 256>>>(out);
}